// round 1
// baseline (speedup 1.0000x reference)
#include <cuda_runtime.h>
#include <cstdint>

#define EPSV 1e-5f
#define BATCH 2048

// ---------------- scratch (device globals; no allocation) ----------------
__device__ uint32_t g_pin1[BATCH * 256];   // conv2 input bits: [b][y*16+x], bit c (32 ch)
__device__ uint32_t g_pin2[BATCH * 128];   // fc1 input bits: [b][word], flatten k = c*64+y*8+x
__device__ uint32_t g_pin3[BATCH * 16];    // fc2 input bits: [b][word] over 512
__device__ float    g_h4[BATCH * 256];     // fc3 input (clipped fp32)
__device__ uint32_t g_wb2[64 * 9];         // conv2 weight bits: [oc][tap], bit c
__device__ uint32_t g_wfc1[512 * 128];     // fc1 weight bits
__device__ uint32_t g_wfc2[256 * 16];      // fc2 weight bits
__device__ float    g_thr2[64];
__device__ float    g_thr3[512];
__device__ float    g_scale4[256];
__device__ float    g_shift4[256];

// ---------------- f32x2 helpers (Blackwell packed fp32) ----------------
__device__ __forceinline__ unsigned long long pack2(float lo, float hi) {
    unsigned long long r;
    asm("mov.b64 %0, {%1, %2};" : "=l"(r) : "f"(lo), "f"(hi));
    return r;
}
__device__ __forceinline__ void unpack2(unsigned long long v, float& lo, float& hi) {
    asm("mov.b64 {%0, %1}, %2;" : "=f"(lo), "=f"(hi) : "l"(v));
}
__device__ __forceinline__ void ffma2(unsigned long long& d, unsigned long long a, unsigned long long b) {
    asm("fma.rn.f32x2 %0, %1, %2, %0;" : "+l"(d) : "l"(a), "l"(b));
}

// ---------------- prep: pack weights as sign bits + fold BN thresholds ----------------
__global__ void __launch_bounds__(256) prep_kernel(
    const float* __restrict__ conv2_w, const float* __restrict__ conv2_b,
    const float* __restrict__ bn2_g, const float* __restrict__ bn2_b,
    const float* __restrict__ bn2_m, const float* __restrict__ bn2_v,
    const float* __restrict__ fc1_w, const float* __restrict__ fc1_b,
    const float* __restrict__ bn3_g, const float* __restrict__ bn3_b,
    const float* __restrict__ bn3_m, const float* __restrict__ bn3_v,
    const float* __restrict__ fc2_w, const float* __restrict__ fc2_b,
    const float* __restrict__ bn4_g, const float* __restrict__ bn4_b,
    const float* __restrict__ bn4_m, const float* __restrict__ bn4_v)
{
    const long FC1N = 512L * 4096L;   // 2097152 (multiple of 256)
    const long FC2N = 256L * 512L;    // 131072
    long tid = (long)blockIdx.x * 256 + threadIdx.x;

    if (tid < FC1N) {
        bool bit = fc1_w[tid] > 0.f;
        uint32_t w = __ballot_sync(0xffffffffu, bit);
        if ((tid & 31) == 0) g_wfc1[tid >> 5] = w;
        return;
    }
    if (tid < FC1N + FC2N) {
        long k = tid - FC1N;
        bool bit = fc2_w[k] > 0.f;
        uint32_t w = __ballot_sync(0xffffffffu, bit);
        if ((k & 31) == 0) g_wfc2[k >> 5] = w;
        return;
    }
    long idx = tid - (FC1N + FC2N);
    if (idx < 576) {
        // conv2 weight word: [oc][tap], bit c (channel stride in memory = 9)
        int oc = (int)idx / 9, tap = (int)idx % 9;
        uint32_t wv = 0;
        for (int c = 0; c < 32; c++)
            if (conv2_w[(oc * 32 + c) * 9 + tap] > 0.f) wv |= (1u << c);
        g_wb2[idx] = wv;
    } else if (idx < 576 + 64) {
        int oc = (int)idx - 576;
        float inv = bn2_g[oc] * rsqrtf(bn2_v[oc] + EPSV);
        float c2 = bn2_b[oc] - bn2_m[oc] * inv;
        g_thr2[oc] = -c2 / inv - conv2_b[oc];          // sign(bn(v+bias)) == v > thr (inv>0)
    } else if (idx < 576 + 64 + 512) {
        int o = (int)idx - (576 + 64);
        float inv = bn3_g[o] * rsqrtf(bn3_v[o] + EPSV);
        float c3 = bn3_b[o] - bn3_m[o] * inv;
        g_thr3[o] = -c3 / inv - fc1_b[o];
    } else if (idx < 576 + 64 + 512 + 256) {
        int o = (int)idx - (576 + 64 + 512);
        float inv = bn4_g[o] * rsqrtf(bn4_v[o] + EPSV);
        float c4 = bn4_b[o] - bn4_m[o] * inv;
        g_scale4[o] = inv;
        g_shift4[o] = fc2_b[o] * inv + c4;
    }
}

// ---------------- conv1 (fp32, ±1 weights) + maxpool + bn1 + sign-pack ----------------
__global__ void __launch_bounds__(256) conv1_kernel(
    const float* __restrict__ x, const float* __restrict__ w, const float* __restrict__ cb,
    const float* __restrict__ g, const float* __restrict__ bb,
    const float* __restrict__ bm, const float* __restrict__ bv)
{
    __shared__ float sx[3][34][34];                 // zero-padded image
    __shared__ unsigned long long sw2[32][27];      // sign weights, pre-broadcast-packed
    __shared__ float thr[32];
    int t = threadIdx.x, b = blockIdx.x;

    for (int i = t; i < 32 * 27; i += 256) {
        float s = (w[i] > 0.f) ? 1.f : -1.f;
        sw2[i / 27][i % 27] = pack2(s, s);
    }
    if (t < 32) {
        float inv = g[t] * rsqrtf(bv[t] + EPSV);
        thr[t] = -(bb[t] - bm[t] * inv) / inv - cb[t];
    }
    const float* xb = x + (long)b * 3 * 32 * 32;
    for (int i = t; i < 3 * 34 * 34; i += 256) {
        int c = i / 1156, r = (i / 34) % 34, cc = i % 34;
        float v = 0.f;
        if (r >= 1 && r <= 32 && cc >= 1 && cc <= 32)
            v = xb[(c * 32 + (r - 1)) * 32 + (cc - 1)];
        sx[c][r][cc] = v;
    }
    __syncthreads();

    int py = t >> 4, px = t & 15;
    // packed input pairs: pk[c][row i][tx] = {patch(i,tx), patch(i,tx+1)}
    unsigned long long pk[3][4][3];
#pragma unroll
    for (int c = 0; c < 3; c++)
#pragma unroll
        for (int i = 0; i < 4; i++)
#pragma unroll
            for (int tx = 0; tx < 3; tx++)
                pk[c][i][tx] = pack2(sx[c][2 * py + i][2 * px + tx],
                                     sx[c][2 * py + i][2 * px + tx + 1]);

    uint32_t word = 0;
#pragma unroll 1
    for (int oc = 0; oc < 32; oc++) {
        unsigned long long a01 = 0ull, a23 = 0ull;   // {s00,s01}, {s10,s11}
#pragma unroll
        for (int c = 0; c < 3; c++)
#pragma unroll
            for (int ty = 0; ty < 3; ty++)
#pragma unroll
                for (int tx = 0; tx < 3; tx++) {
                    unsigned long long wv = sw2[oc][(c * 3 + ty) * 3 + tx];
                    ffma2(a01, pk[c][ty][tx], wv);
                    ffma2(a23, pk[c][ty + 1][tx], wv);
                }
        float s0, s1, s2, s3;
        unpack2(a01, s0, s1);
        unpack2(a23, s2, s3);
        float mx = fmaxf(fmaxf(s0, s1), fmaxf(s2, s3));
        if (mx > thr[oc]) word |= (1u << oc);
    }
    g_pin1[b * 256 + t] = word;
}

// ---------------- conv2 (binary x binary, popcount) + pool + bn2 + sign-pack ----------------
__global__ void __launch_bounds__(256) conv2_kernel()
{
    __shared__ uint32_t tile[16][16];
    __shared__ uint32_t wb[64][9];
    __shared__ float thr[64];
    int t = threadIdx.x, b = blockIdx.x;

    for (int i = t; i < 576; i += 256) wb[i / 9][i % 9] = g_wb2[i];
    if (t < 64) thr[t] = g_thr2[t];
    tile[t >> 4][t & 15] = g_pin1[b * 256 + t];
    __syncthreads();

    for (int iter = 0; iter < 16; iter++) {
        int idx = iter * 256 + t;                 // flatten k = oc*64 + py*8 + px
        int oc = idx >> 6, py = (idx >> 3) & 7, px = idx & 7;
        uint32_t wr[9];
#pragma unroll
        for (int k = 0; k < 9; k++) wr[k] = wb[oc][k];   // warp-uniform broadcast

        int best = -100000;
#pragma unroll
        for (int dy = 0; dy < 2; dy++)
#pragma unroll
            for (int dx = 0; dx < 2; dx++) {
                int y = 2 * py + dy, x = 2 * px + dx;
                int acc = 0;                      // accumulates (16 - popc); true dot = 2*acc
#pragma unroll
                for (int ty = 0; ty < 3; ty++) {
                    int yy = y + ty - 1;
                    if (yy < 0 || yy > 15) continue;
#pragma unroll
                    for (int tx = 0; tx < 3; tx++) {
                        int xx = x + tx - 1;
                        if (xx < 0 || xx > 15) continue;
                        acc += 16 - __popc(tile[yy][xx] ^ wr[ty * 3 + tx]);
                    }
                }
                best = max(best, acc);
            }
        bool bit = (2.f * (float)best) > thr[oc];
        uint32_t wm = __ballot_sync(0xffffffffu, bit);
        if ((t & 31) == 0) g_pin2[b * 128 + (idx >> 5)] = wm;
    }
}

// ---------------- fc1: 2048x512 binary GEMM (K=4096 bits) + bn3 + sign-pack ----------------
__global__ void __launch_bounds__(256) fc1_kernel()
{
    __shared__ uint32_t As[64][65];
    __shared__ uint32_t Ws[64][65];
    __shared__ float thr[64];
    __shared__ uint32_t packbuf[64][2];
    int t = threadIdx.x;
    int bt = blockIdx.x;   // 32 b-tiles of 64
    int ot = blockIdx.y;   // 8 o-tiles of 64

    if (t < 64) thr[t] = g_thr3[ot * 64 + t];
    if (t < 128) packbuf[t >> 1][t & 1] = 0u;

    int tx = t & 15, ty = t >> 4;
    int cnt[4][4];
#pragma unroll
    for (int i = 0; i < 4; i++)
#pragma unroll
        for (int j = 0; j < 4; j++) cnt[i][j] = 0;

    for (int kc = 0; kc < 2; kc++) {
        __syncthreads();
        for (int i = t; i < 64 * 64; i += 256) {
            int r = i >> 6, k = i & 63;
            As[r][k] = g_pin2[(bt * 64 + r) * 128 + kc * 64 + k];
            Ws[r][k] = g_wfc1[(ot * 64 + r) * 128 + kc * 64 + k];
        }
        __syncthreads();
#pragma unroll 4
        for (int k = 0; k < 64; k++) {
            uint32_t a0 = As[ty * 4 + 0][k], a1 = As[ty * 4 + 1][k];
            uint32_t a2 = As[ty * 4 + 2][k], a3 = As[ty * 4 + 3][k];
            uint32_t w0 = Ws[tx * 4 + 0][k], w1 = Ws[tx * 4 + 1][k];
            uint32_t w2 = Ws[tx * 4 + 2][k], w3 = Ws[tx * 4 + 3][k];
            cnt[0][0] += __popc(a0 ^ w0); cnt[0][1] += __popc(a0 ^ w1);
            cnt[0][2] += __popc(a0 ^ w2); cnt[0][3] += __popc(a0 ^ w3);
            cnt[1][0] += __popc(a1 ^ w0); cnt[1][1] += __popc(a1 ^ w1);
            cnt[1][2] += __popc(a1 ^ w2); cnt[1][3] += __popc(a1 ^ w3);
            cnt[2][0] += __popc(a2 ^ w0); cnt[2][1] += __popc(a2 ^ w1);
            cnt[2][2] += __popc(a2 ^ w2); cnt[2][3] += __popc(a2 ^ w3);
            cnt[3][0] += __popc(a3 ^ w0); cnt[3][1] += __popc(a3 ^ w1);
            cnt[3][2] += __popc(a3 ^ w2); cnt[3][3] += __popc(a3 ^ w3);
        }
    }
#pragma unroll
    for (int i = 0; i < 4; i++) {
        int bl = ty * 4 + i;
        uint32_t nib = 0;
#pragma unroll
        for (int j = 0; j < 4; j++) {
            float val = 4096.f - 2.f * (float)cnt[i][j];
            if (val > thr[tx * 4 + j]) nib |= (1u << j);
        }
        atomicOr(&packbuf[bl][tx >> 3], nib << ((tx * 4) & 31));
    }
    __syncthreads();
    if (t < 128)
        g_pin3[(bt * 64 + (t >> 1)) * 16 + ot * 2 + (t & 1)] = packbuf[t >> 1][t & 1];
}

// ---------------- fc2: binary GEMM (K=512 bits) + bn4 + clip -> fp32 ----------------
__global__ void __launch_bounds__(256) fc2_kernel()
{
    __shared__ uint32_t sA[16];
    __shared__ uint32_t sW[256][17];
    __shared__ float ssc[256], ssh[256];
    int b = blockIdx.x, t = threadIdx.x;

    if (t < 16) sA[t] = g_pin3[b * 16 + t];
    ssc[t] = g_scale4[t];
    ssh[t] = g_shift4[t];
    for (int i = t; i < 4096; i += 256) sW[i >> 4][i & 15] = g_wfc2[i];
    __syncthreads();

    int cnt = 0;
#pragma unroll
    for (int k = 0; k < 16; k++) cnt += __popc(sA[k] ^ sW[t][k]);
    float val = 512.f - 2.f * (float)cnt;
    float o = val * ssc[t] + ssh[t];
    o = fminf(fmaxf(o, -1.f), 1.f);
    g_h4[b * 256 + t] = o;
}

// ---------------- fc3 (fp32) + log_softmax ----------------
__global__ void __launch_bounds__(256) fc3_kernel(
    const float* __restrict__ w, const float* __restrict__ bias, float* __restrict__ out)
{
    int warp = threadIdx.x >> 5, lane = threadIdx.x & 31;
    int b = blockIdx.x * 8 + warp;
    const float* h = g_h4 + (long)b * 256;

    float acc[10];
#pragma unroll
    for (int j = 0; j < 10; j++) acc[j] = 0.f;

    for (int k = lane; k < 256; k += 32) {
        float hv = h[k];
#pragma unroll
        for (int j = 0; j < 10; j++) acc[j] += hv * w[j * 256 + k];
    }
#pragma unroll
    for (int j = 0; j < 10; j++)
#pragma unroll
        for (int off = 16; off; off >>= 1)
            acc[j] += __shfl_xor_sync(0xffffffffu, acc[j], off);

    if (lane == 0) {
        float l[10], mx = -1e30f;
#pragma unroll
        for (int j = 0; j < 10; j++) { l[j] = acc[j] + bias[j]; mx = fmaxf(mx, l[j]); }
        float s = 0.f;
#pragma unroll
        for (int j = 0; j < 10; j++) s += __expf(l[j] - mx);
        float lse = mx + __logf(s);
#pragma unroll
        for (int j = 0; j < 10; j++) out[b * 10 + j] = l[j] - lse;
    }
}

// ---------------- launch ----------------
extern "C" void kernel_launch(void* const* d_in, const int* in_sizes, int n_in,
                              void* d_out, int out_size)
{
    const float* x       = (const float*)d_in[0];
    const float* conv1_w = (const float*)d_in[1];
    const float* conv1_b = (const float*)d_in[2];
    const float* bn1_g   = (const float*)d_in[3];
    const float* bn1_b   = (const float*)d_in[4];
    const float* bn1_m   = (const float*)d_in[5];
    const float* bn1_v   = (const float*)d_in[6];
    const float* conv2_w = (const float*)d_in[7];
    const float* conv2_b = (const float*)d_in[8];
    const float* bn2_g   = (const float*)d_in[9];
    const float* bn2_b   = (const float*)d_in[10];
    const float* bn2_m   = (const float*)d_in[11];
    const float* bn2_v   = (const float*)d_in[12];
    const float* fc1_w   = (const float*)d_in[13];
    const float* fc1_b   = (const float*)d_in[14];
    const float* bn3_g   = (const float*)d_in[15];
    const float* bn3_b   = (const float*)d_in[16];
    const float* bn3_m   = (const float*)d_in[17];
    const float* bn3_v   = (const float*)d_in[18];
    const float* fc2_w   = (const float*)d_in[19];
    const float* fc2_b   = (const float*)d_in[20];
    const float* bn4_g   = (const float*)d_in[21];
    const float* bn4_b   = (const float*)d_in[22];
    const float* bn4_m   = (const float*)d_in[23];
    const float* bn4_v   = (const float*)d_in[24];
    const float* fc3_w   = (const float*)d_in[25];
    const float* fc3_b   = (const float*)d_in[26];

    // total prep work items = 512*4096 + 256*512 + 576 + 64 + 512 + 256 = 2229632
    int prep_blocks = (2229632 + 255) / 256;   // 8710
    prep_kernel<<<prep_blocks, 256>>>(conv2_w, conv2_b, bn2_g, bn2_b, bn2_m, bn2_v,
                                      fc1_w, fc1_b, bn3_g, bn3_b, bn3_m, bn3_v,
                                      fc2_w, fc2_b, bn4_g, bn4_b, bn4_m, bn4_v);
    conv1_kernel<<<BATCH, 256>>>(x, conv1_w, conv1_b, bn1_g, bn1_b, bn1_m, bn1_v);
    conv2_kernel<<<BATCH, 256>>>();
    fc1_kernel<<<dim3(32, 8), 256>>>();
    fc2_kernel<<<BATCH, 256>>>();
    fc3_kernel<<<BATCH / 8, 256>>>(fc3_w, fc3_b, (float*)d_out);
}

// round 2
// speedup vs baseline: 1.0114x; 1.0114x over previous
#include <cuda_runtime.h>
#include <cstdint>

#define EPSV 1e-5f
#define BATCH 2048

// ---------------- scratch (device globals; no allocation) ----------------
__device__ uint32_t g_pin2T[128 * BATCH];  // fc1 input bits, K-major: [word k][batch]
__device__ uint32_t g_pin3[BATCH * 16];    // fc2 input bits: [b][word] over 512
__device__ uint32_t g_wb2[64 * 9];         // conv2 weight bits: [oc][tap], bit c
__device__ uint32_t g_wfc1T[128 * 512];    // fc1 weight bits, K-major: [word k][out]
__device__ uint32_t g_wfc2[256 * 16];      // fc2 weight bits: [o][word]
__device__ float    g_thr2[64];
__device__ float    g_thr3[512];
__device__ float    g_scale4[256];
__device__ float    g_shift4[256];

// ---------------- f32x2 helpers (Blackwell packed fp32) ----------------
__device__ __forceinline__ unsigned long long pack2(float lo, float hi) {
    unsigned long long r;
    asm("mov.b64 %0, {%1, %2};" : "=l"(r) : "f"(lo), "f"(hi));
    return r;
}
__device__ __forceinline__ void unpack2(unsigned long long v, float& lo, float& hi) {
    asm("mov.b64 {%0, %1}, %2;" : "=f"(lo), "=f"(hi) : "l"(v));
}
__device__ __forceinline__ void ffma2(unsigned long long& d, unsigned long long a, unsigned long long b) {
    asm("fma.rn.f32x2 %0, %1, %2, %0;" : "+l"(d) : "l"(a), "l"(b));
}

// ---------------- prep: pack weights + fold BN thresholds ----------------
__global__ void __launch_bounds__(256) prep_kernel(
    const float* __restrict__ conv2_w, const float* __restrict__ conv2_b,
    const float* __restrict__ bn2_g, const float* __restrict__ bn2_b,
    const float* __restrict__ bn2_m, const float* __restrict__ bn2_v,
    const float* __restrict__ fc1_w, const float* __restrict__ fc1_b,
    const float* __restrict__ bn3_g, const float* __restrict__ bn3_b,
    const float* __restrict__ bn3_m, const float* __restrict__ bn3_v,
    const float* __restrict__ fc2_w, const float* __restrict__ fc2_b,
    const float* __restrict__ bn4_g, const float* __restrict__ bn4_b,
    const float* __restrict__ bn4_m, const float* __restrict__ bn4_v)
{
    const long FC1N = 512L * 4096L;   // multiple of 256
    const long FC2N = 256L * 512L;
    long tid = (long)blockIdx.x * 256 + threadIdx.x;

    if (tid < FC1N) {
        int o = (int)(tid >> 12);
        int k = (int)(tid & 4095);
        bool bit = fc1_w[tid] > 0.f;
        uint32_t w = __ballot_sync(0xffffffffu, bit);
        if ((k & 31) == 0) g_wfc1T[(k >> 5) * 512 + o] = w;   // K-major
        return;
    }
    if (tid < FC1N + FC2N) {
        long k = tid - FC1N;
        bool bit = fc2_w[k] > 0.f;
        uint32_t w = __ballot_sync(0xffffffffu, bit);
        if ((k & 31) == 0) g_wfc2[k >> 5] = w;
        return;
    }
    long idx = tid - (FC1N + FC2N);
    if (idx < 576) {
        int oc = (int)idx / 9, tap = (int)idx % 9;
        uint32_t wv = 0;
        for (int c = 0; c < 32; c++)
            if (conv2_w[(oc * 32 + c) * 9 + tap] > 0.f) wv |= (1u << c);
        g_wb2[idx] = wv;
    } else if (idx < 576 + 64) {
        int oc = (int)idx - 576;
        float inv = bn2_g[oc] * rsqrtf(bn2_v[oc] + EPSV);
        float c2 = bn2_b[oc] - bn2_m[oc] * inv;
        g_thr2[oc] = -c2 / inv - conv2_b[oc];
    } else if (idx < 576 + 64 + 512) {
        int o = (int)idx - (576 + 64);
        float inv = bn3_g[o] * rsqrtf(bn3_v[o] + EPSV);
        float c3 = bn3_b[o] - bn3_m[o] * inv;
        g_thr3[o] = -c3 / inv - fc1_b[o];
    } else if (idx < 576 + 64 + 512 + 256) {
        int o = (int)idx - (576 + 64 + 512);
        float inv = bn4_g[o] * rsqrtf(bn4_v[o] + EPSV);
        float c4 = bn4_b[o] - bn4_m[o] * inv;
        g_scale4[o] = inv;
        g_shift4[o] = fc2_b[o] * inv + c4;
    }
}

// ---------------- fused conv1 (fp32 FFMA2) + pool/bn/sign + conv2 (XNOR-popc) + pool/bn/sign ----------------
__global__ void __launch_bounds__(256, 2) convfused_kernel(
    const float* __restrict__ x, const float* __restrict__ w, const float* __restrict__ cb,
    const float* __restrict__ g, const float* __restrict__ bb,
    const float* __restrict__ bm, const float* __restrict__ bv)
{
    __shared__ float sx[3][34][34];                 // zero-padded image
    __shared__ unsigned long long sw2[32][27];      // conv1 sign weights, broadcast-packed
    __shared__ float thr1[32];
    __shared__ uint32_t tile[16][16];               // conv1 output bitplane
    __shared__ uint32_t wb[64][9];                  // conv2 weight bits
    __shared__ float thr2s[64];
    __shared__ uint32_t mbits[64][4];               // pooled bits staging

    int t = threadIdx.x, b = blockIdx.x;

    // ---- load phase ----
    for (int i = t; i < 32 * 27; i += 256) {
        float s = (w[i] > 0.f) ? 1.f : -1.f;
        sw2[i / 27][i % 27] = pack2(s, s);
    }
    if (t < 32) {
        float inv = g[t] * rsqrtf(bv[t] + EPSV);
        thr1[t] = -(bb[t] - bm[t] * inv) / inv - cb[t];
    }
    for (int i = t; i < 576; i += 256) wb[i / 9][i % 9] = g_wb2[i];
    if (t >= 64 && t < 128) thr2s[t - 64] = g_thr2[t - 64];
    const float* xb = x + (long)b * 3 * 32 * 32;
    for (int i = t; i < 3 * 34 * 34; i += 256) {
        int c = i / 1156, r = (i / 34) % 34, cc = i % 34;
        float v = 0.f;
        if (r >= 1 && r <= 32 && cc >= 1 && cc <= 32)
            v = xb[(c * 32 + (r - 1)) * 32 + (cc - 1)];
        sx[c][r][cc] = v;
    }
    __syncthreads();

    // ---- conv1 phase: thread t owns pooled pixel (py,px) of 16x16 ----
    {
        int py = t >> 4, px = t & 15;
        unsigned long long pk[3][4][3];
#pragma unroll
        for (int c = 0; c < 3; c++)
#pragma unroll
            for (int i = 0; i < 4; i++)
#pragma unroll
                for (int tx = 0; tx < 3; tx++)
                    pk[c][i][tx] = pack2(sx[c][2 * py + i][2 * px + tx],
                                         sx[c][2 * py + i][2 * px + tx + 1]);

        uint32_t word = 0;
#pragma unroll 1
        for (int oc = 0; oc < 32; oc++) {
            unsigned long long a01 = 0ull, a23 = 0ull;
#pragma unroll
            for (int c = 0; c < 3; c++)
#pragma unroll
                for (int ty = 0; ty < 3; ty++)
#pragma unroll
                    for (int tx = 0; tx < 3; tx++) {
                        unsigned long long wv = sw2[oc][(c * 3 + ty) * 3 + tx];
                        ffma2(a01, pk[c][ty][tx], wv);
                        ffma2(a23, pk[c][ty + 1][tx], wv);
                    }
            float s0, s1, s2, s3;
            unpack2(a01, s0, s1);
            unpack2(a23, s2, s3);
            float mx = fmaxf(fmaxf(s0, s1), fmaxf(s2, s3));
            if (mx > thr1[oc]) word |= (1u << oc);
        }
        tile[py][px] = word;
    }
    __syncthreads();

    // ---- conv2 phase: thread = (pooled pos, oc-group of 16) ----
    {
        int pos = t >> 2, gg = t & 3;
        int py = pos >> 3, px = pos & 7;

        uint32_t nb[4][4], vm[4][4];
#pragma unroll
        for (int i = 0; i < 4; i++) {
            int ry = 2 * py - 1 + i;
#pragma unroll
            for (int jx = 0; jx < 4; jx++) {
                int cx = 2 * px - 1 + jx;
                bool ok = (ry >= 0) && (ry < 16) && (cx >= 0) && (cx < 16);
                nb[i][jx] = ok ? tile[ry][cx] : 0u;
                vm[i][jx] = ok ? 0xffffffffu : 0u;
            }
        }
        int nv[2][2];
#pragma unroll
        for (int dy = 0; dy < 2; dy++)
#pragma unroll
            for (int dx = 0; dx < 2; dx++) {
                int c = 0;
#pragma unroll
                for (int ty = 0; ty < 3; ty++)
#pragma unroll
                    for (int tx = 0; tx < 3; tx++)
                        c += (int)(vm[dy + ty][dx + tx] & 1u);
                nv[dy][dx] = 16 * c;
            }

        uint32_t mask = 0;
#pragma unroll 1
        for (int i16 = 0; i16 < 16; i16++) {
            int oc = gg * 16 + i16;
            uint32_t wr[9];
#pragma unroll
            for (int k = 0; k < 9; k++) wr[k] = wb[oc][k];
            int maxv = -1000000;
#pragma unroll
            for (int dy = 0; dy < 2; dy++)
#pragma unroll
                for (int dx = 0; dx < 2; dx++) {
                    int s = 0;
#pragma unroll
                    for (int ty = 0; ty < 3; ty++)
#pragma unroll
                        for (int tx = 0; tx < 3; tx++)
                            s += __popc((nb[dy + ty][dx + tx] ^ wr[ty * 3 + tx]) & vm[dy + ty][dx + tx]);
                    int valj = nv[dy][dx] - s;      // dot = 2*valj
                    maxv = max(maxv, valj);
                }
            if ((float)maxv > 0.5f * thr2s[oc]) mask |= (1u << i16);
        }
        mbits[pos][gg] = mask;
    }
    __syncthreads();

    // ---- assemble 128 output words (k = oc*64 + pos), write K-major ----
    if (t < 128) {
        int oc = t >> 1, half = t & 1;
        int grp = oc >> 4, bi = oc & 15;
        uint32_t wrd = 0;
#pragma unroll
        for (int p = 0; p < 32; p++)
            wrd |= ((mbits[half * 32 + p][grp] >> bi) & 1u) << p;
        g_pin2T[t * BATCH + b] = wrd;
    }
}

// ---------------- fc1: 2048x512 binary GEMM (K=4096 bits), vec4 smem ----------------
__global__ void __launch_bounds__(256) fc1_kernel()
{
    __shared__ __align__(16) uint32_t As[64][64];   // [k][m]
    __shared__ __align__(16) uint32_t Ws[64][64];   // [k][n]
    __shared__ float thr[64];
    __shared__ uint32_t packbuf[64][2];
    int t = threadIdx.x;
    int bt = blockIdx.x;   // 32 b-tiles of 64
    int ot = blockIdx.y;   // 8 o-tiles of 64

    if (t < 64) thr[t] = g_thr3[ot * 64 + t];
    if (t < 128) packbuf[t >> 1][t & 1] = 0u;

    int tx = t & 15, ty = t >> 4;    // n-block = tx*4, m-block = ty*4
    int cnt[4][4];
#pragma unroll
    for (int i = 0; i < 4; i++)
#pragma unroll
        for (int j = 0; j < 4; j++) cnt[i][j] = 0;

    for (int kc = 0; kc < 2; kc++) {
        __syncthreads();
        for (int i = t; i < 64 * 64; i += 256) {
            int k = i >> 6, m = i & 63;
            As[k][m] = g_pin2T[(kc * 64 + k) * BATCH + bt * 64 + m];
            Ws[k][m] = g_wfc1T[(kc * 64 + k) * 512 + ot * 64 + m];
        }
        __syncthreads();
#pragma unroll 2
        for (int k = 0; k < 64; k++) {
            uint4 av = *reinterpret_cast<const uint4*>(&As[k][ty * 4]);
            uint4 wv = *reinterpret_cast<const uint4*>(&Ws[k][tx * 4]);
            uint32_t a[4] = {av.x, av.y, av.z, av.w};
            uint32_t wr[4] = {wv.x, wv.y, wv.z, wv.w};
#pragma unroll
            for (int i = 0; i < 4; i++)
#pragma unroll
                for (int j = 0; j < 4; j++)
                    cnt[i][j] += __popc(a[i] ^ wr[j]);
        }
    }
#pragma unroll
    for (int i = 0; i < 4; i++) {
        int bl = ty * 4 + i;
        uint32_t nib = 0;
#pragma unroll
        for (int j = 0; j < 4; j++) {
            float val = 4096.f - 2.f * (float)cnt[i][j];
            if (val > thr[tx * 4 + j]) nib |= (1u << j);
        }
        atomicOr(&packbuf[bl][tx >> 3], nib << ((tx * 4) & 31));
    }
    __syncthreads();
    if (t < 128)
        g_pin3[(bt * 64 + (t >> 1)) * 16 + ot * 2 + (t & 1)] = packbuf[t >> 1][t & 1];
}

// ---------------- head: fc2 (binary, K=512) + bn4 + clip + fc3 + log_softmax ----------------
__global__ void __launch_bounds__(256) head_kernel(
    const float* __restrict__ w3, const float* __restrict__ b3, float* __restrict__ out)
{
    __shared__ uint32_t sW2[16][256];   // [k][o] conflict-free per-lane rows
    __shared__ uint32_t sA[8][16];
    __shared__ float sH[8][256];
    __shared__ float sW3[2560];
    __shared__ float sb3[10];
    int t = threadIdx.x;
    int b0 = blockIdx.x * 8;

    for (int i = t; i < 4096; i += 256) {
        int k = i >> 8, o = i & 255;
        sW2[k][o] = g_wfc2[o * 16 + k];
    }
    if (t < 128) sA[t >> 4][t & 15] = g_pin3[(b0 + (t >> 4)) * 16 + (t & 15)];
    for (int i = t; i < 2560; i += 256) sW3[i] = w3[i];
    if (t < 10) sb3[t] = b3[t];
    __syncthreads();

    // fc2: thread t = output o, loop 8 images
    {
        uint32_t wr[16];
#pragma unroll
        for (int k = 0; k < 16; k++) wr[k] = sW2[k][t];
        float sc = g_scale4[t], sh = g_shift4[t];
#pragma unroll
        for (int img = 0; img < 8; img++) {
            int c = 0;
#pragma unroll
            for (int k = 0; k < 16; k++) c += __popc(sA[img][k] ^ wr[k]);
            float val = 512.f - 2.f * (float)c;
            float o = val * sc + sh;
            sH[img][t] = fminf(fmaxf(o, -1.f), 1.f);
        }
    }
    __syncthreads();

    // fc3: warp per image
    {
        int img = t >> 5, lane = t & 31;
        float acc[10];
#pragma unroll
        for (int j = 0; j < 10; j++) acc[j] = 0.f;
#pragma unroll
        for (int d8 = 0; d8 < 8; d8++) {
            float hv = sH[img][d8 * 32 + lane];
#pragma unroll
            for (int j = 0; j < 10; j++) acc[j] += hv * sW3[j * 256 + d8 * 32 + lane];
        }
#pragma unroll
        for (int j = 0; j < 10; j++)
#pragma unroll
            for (int off = 16; off; off >>= 1)
                acc[j] += __shfl_xor_sync(0xffffffffu, acc[j], off);

        if (lane == 0) {
            float l[10], mx = -1e30f;
#pragma unroll
            for (int j = 0; j < 10; j++) { l[j] = acc[j] + sb3[j]; mx = fmaxf(mx, l[j]); }
            float s = 0.f;
#pragma unroll
            for (int j = 0; j < 10; j++) s += __expf(l[j] - mx);
            float lse = mx + __logf(s);
#pragma unroll
            for (int j = 0; j < 10; j++) out[(b0 + img) * 10 + j] = l[j] - lse;
        }
    }
}

// ---------------- launch ----------------
extern "C" void kernel_launch(void* const* d_in, const int* in_sizes, int n_in,
                              void* d_out, int out_size)
{
    const float* x       = (const float*)d_in[0];
    const float* conv1_w = (const float*)d_in[1];
    const float* conv1_b = (const float*)d_in[2];
    const float* bn1_g   = (const float*)d_in[3];
    const float* bn1_b   = (const float*)d_in[4];
    const float* bn1_m   = (const float*)d_in[5];
    const float* bn1_v   = (const float*)d_in[6];
    const float* conv2_w = (const float*)d_in[7];
    const float* conv2_b = (const float*)d_in[8];
    const float* bn2_g   = (const float*)d_in[9];
    const float* bn2_b   = (const float*)d_in[10];
    const float* bn2_m   = (const float*)d_in[11];
    const float* bn2_v   = (const float*)d_in[12];
    const float* fc1_w   = (const float*)d_in[13];
    const float* fc1_b   = (const float*)d_in[14];
    const float* bn3_g   = (const float*)d_in[15];
    const float* bn3_b   = (const float*)d_in[16];
    const float* bn3_m   = (const float*)d_in[17];
    const float* bn3_v   = (const float*)d_in[18];
    const float* fc2_w   = (const float*)d_in[19];
    const float* fc2_b   = (const float*)d_in[20];
    const float* bn4_g   = (const float*)d_in[21];
    const float* bn4_b   = (const float*)d_in[22];
    const float* bn4_m   = (const float*)d_in[23];
    const float* bn4_v   = (const float*)d_in[24];
    const float* fc3_w   = (const float*)d_in[25];
    const float* fc3_b   = (const float*)d_in[26];

    int prep_blocks = (2229632 + 255) / 256;
    prep_kernel<<<prep_blocks, 256>>>(conv2_w, conv2_b, bn2_g, bn2_b, bn2_m, bn2_v,
                                      fc1_w, fc1_b, bn3_g, bn3_b, bn3_m, bn3_v,
                                      fc2_w, fc2_b, bn4_g, bn4_b, bn4_m, bn4_v);
    convfused_kernel<<<BATCH, 256>>>(x, conv1_w, conv1_b, bn1_g, bn1_b, bn1_m, bn1_v);
    fc1_kernel<<<dim3(32, 8), 256>>>();
    head_kernel<<<BATCH / 8, 256>>>(fc3_w, fc3_b, (float*)d_out);
}